// round 6
// baseline (speedup 1.0000x reference)
#include <cuda_runtime.h>

#define TPB     384
#define NODES   32
#define KU      16                  // u per chunk
#define NCHUNK  8
#define XS      148                 // floats per node per chunk: x0(16)+x1(48)+x2(80)+pad(4)
#define XBUF    (NODES * XS)        // 4736 floats per buffer
#define OFF_W0  (3 * XBUF)          // w1_0: 6144 floats
#define OFF_W1  (OFF_W0 + 6144)
#define OFF_W2  (OFF_W1 + 2048)
#define OFF_W2S (OFF_W2 + 2048)
#define SM_FLOATS (OFF_W2S + 48)    // 24496 floats = 97984 B -> 2 blocks/SM

typedef unsigned long long u64;

__device__ __forceinline__ u64 ffma2(u64 a, u64 b, u64 c) {
    u64 d;
    asm("fma.rn.f32x2 %0, %1, %2, %3;" : "=l"(d) : "l"(a), "l"(b), "l"(c));
    return d;
}
__device__ __forceinline__ u64 dup2(float v) {
    u64 d; unsigned u = __float_as_uint(v);
    asm("mov.b64 %0, {%1, %1};" : "=l"(d) : "r"(u));
    return d;
}
__device__ __forceinline__ void unpack2(u64 a, float& lo, float& hi) {
    lo = __uint_as_float((unsigned)a);
    hi = __uint_as_float((unsigned)(a >> 32));
}

__global__ void __launch_bounds__(TPB, 2)
readout_kernel(const float* __restrict__ x,
               const float* __restrict__ w1_0, const float* __restrict__ w1_1,
               const float* __restrict__ w1_2, const float* __restrict__ w2_0,
               const float* __restrict__ w2_1, const float* __restrict__ w2_2,
               float* __restrict__ out, int n)
{
    extern __shared__ float sm[];
    const int tid = threadIdx.x;
    const int node0 = blockIdx.x * NODES;
    const unsigned smbase = (unsigned)__cvta_generic_to_shared(sm);

    // ---- per-thread cp.async staging constants (3 x 16B per thread per chunk) ----
    // per node per chunk: 36 x 16B = x0(4) + x1(12) + x2(20)
    int gnd[3], sb[3], sc[3];
    unsigned sdst[3];
#pragma unroll
    for (int k = 0; k < 3; ++k) {
        int f = tid + k * TPB;
        int nd = f / 36, r = f - nd * 36;
        int dl;
        if (r < 4)       { sb[k] = 4 * r;               sc[k] = 16; dl = 4 * r; }
        else if (r < 16) { sb[k] = 128 + 4 * (r - 4);   sc[k] = 48; dl = 16 + 4 * (r - 4); }
        else             { sb[k] = 512 + 4 * (r - 16);  sc[k] = 80; dl = 64 + 4 * (r - 16); }
        int gn = node0 + nd;
        gnd[k] = (gn < n) ? gn : (n - 1);   // clamp (duplicate read; stores are guarded)
        sdst[k] = (unsigned)((nd * XS + dl) * 4);
    }
    auto stage = [&](int c, int buf) {
#pragma unroll
        for (int k = 0; k < 3; ++k) {
            const float* src = x + (size_t)gnd[k] * 1152 + sb[k] + sc[k] * c;
            unsigned dst = smbase + (unsigned)(buf * XBUF * 4) + sdst[k];
            asm volatile("cp.async.cg.shared.global [%0], [%1], 16;"
                         :: "r"(dst), "l"(src));
        }
    };

    stage(0, 0); asm volatile("cp.async.commit_group;" ::: "memory");
    stage(1, 1); asm volatile("cp.async.commit_group;" ::: "memory");

    for (int i = tid; i < 6144; i += TPB) sm[OFF_W0 + i] = w1_0[i];
    for (int i = tid; i < 2048; i += TPB) sm[OFF_W1 + i] = w1_1[i];
    for (int i = tid; i < 2048; i += TPB) sm[OFF_W2 + i] = w1_2[i];
    if (tid < 16) {
        sm[OFF_W2S + tid]      = w2_0[tid];
        sm[OFF_W2S + 16 + tid] = w2_1[tid];
        sm[OFF_W2S + 32 + tid] = w2_2[tid];
    }

    // warp roles: type = which GEMV; (uhalf, vhalf) 2x2 split.
    // SMSP = w&3 gets exactly one warp of each type -> balanced FMA load.
    const int w     = tid >> 5;
    const int lane  = tid & 31;
    const int type  = w >> 2;        // 0:y0 1:y1 2:y2
    const int uhalf = (w >> 1) & 1;
    const int vhalf = w & 1;
    const int node  = lane;

    u64 A[20];
#pragma unroll
    for (int i = 0; i < 20; ++i) A[i] = 0ull;

#pragma unroll 1
    for (int c = 0; c < NCHUNK; ++c) {
        if (c == NCHUNK - 1) asm volatile("cp.async.wait_group 0;" ::: "memory");
        else                 asm volatile("cp.async.wait_group 1;" ::: "memory");
        __syncthreads();
        if (c < NCHUNK - 2) {
            stage(c + 2, (c + 2) % 3);
            asm volatile("cp.async.commit_group;" ::: "memory");
        }
        const float* xr = sm + (c % 3) * XBUF + node * XS;
        const int u0 = KU * c + uhalf * 8;     // global u of this warp's 8-u slice

        if (type == 0) {
            // y0: 24 outputs (vhalf*24 .. +23) as 12 f32x2 pairs
            const int v0 = vhalf * 24;
#pragma unroll
            for (int g = 0; g < 2; ++g) {
                float4 xv = *(const float4*)(xr + uhalf * 8 + 4 * g);
                float xe[4] = { xv.x, xv.y, xv.z, xv.w };
#pragma unroll
                for (int du = 0; du < 4; ++du) {
                    u64 xs2 = dup2(xe[du]);
                    const ulonglong2* wp =
                        (const ulonglong2*)(sm + OFF_W0 + (u0 + 4 * g + du) * 48 + v0);
                    ulonglong2 p0 = wp[0], p1 = wp[1], p2 = wp[2],
                               p3 = wp[3], p4 = wp[4], p5 = wp[5];
                    A[0]  = ffma2(xs2, p0.x, A[0]);  A[1]  = ffma2(xs2, p0.y, A[1]);
                    A[2]  = ffma2(xs2, p1.x, A[2]);  A[3]  = ffma2(xs2, p1.y, A[3]);
                    A[4]  = ffma2(xs2, p2.x, A[4]);  A[5]  = ffma2(xs2, p2.y, A[5]);
                    A[6]  = ffma2(xs2, p3.x, A[6]);  A[7]  = ffma2(xs2, p3.y, A[7]);
                    A[8]  = ffma2(xs2, p4.x, A[8]);  A[9]  = ffma2(xs2, p4.y, A[9]);
                    A[10] = ffma2(xs2, p5.x, A[10]); A[11] = ffma2(xs2, p5.y, A[11]);
                }
            }
        } else if (type == 1) {
            // y1: 8 v (vhalf*8..+7) x i=0..2 -> A[i*4+vp]
            const int v0 = vhalf * 8;
#pragma unroll
            for (int h = 0; h < 2; ++h) {
                const float4* xp = (const float4*)(xr + 16 + uhalf * 24 + h * 12);
                float4 q0 = xp[0], q1 = xp[1], q2 = xp[2];
                float xe[12] = { q0.x,q0.y,q0.z,q0.w, q1.x,q1.y,q1.z,q1.w,
                                 q2.x,q2.y,q2.z,q2.w };
#pragma unroll
                for (int ul = 0; ul < 4; ++ul) {
                    const ulonglong2* wp =
                        (const ulonglong2*)(sm + OFF_W1 + (u0 + h * 4 + ul) * 16 + v0);
                    ulonglong2 wa = wp[0], wb = wp[1];
#pragma unroll
                    for (int i = 0; i < 3; ++i) {
                        u64 xs2 = dup2(xe[ul * 3 + i]);
                        A[i * 4 + 0] = ffma2(xs2, wa.x, A[i * 4 + 0]);
                        A[i * 4 + 1] = ffma2(xs2, wa.y, A[i * 4 + 1]);
                        A[i * 4 + 2] = ffma2(xs2, wb.x, A[i * 4 + 2]);
                        A[i * 4 + 3] = ffma2(xs2, wb.y, A[i * 4 + 3]);
                    }
                }
            }
        } else {
            // y2: 8 v x i=0..4 -> A[i*4+vp]
            const int v0 = vhalf * 8;
#pragma unroll
            for (int h = 0; h < 2; ++h) {
                const float4* xp = (const float4*)(xr + 64 + uhalf * 40 + h * 20);
                float4 q0 = xp[0], q1 = xp[1], q2 = xp[2], q3 = xp[3], q4 = xp[4];
                float xe[20] = { q0.x,q0.y,q0.z,q0.w, q1.x,q1.y,q1.z,q1.w,
                                 q2.x,q2.y,q2.z,q2.w, q3.x,q3.y,q3.z,q3.w,
                                 q4.x,q4.y,q4.z,q4.w };
#pragma unroll
                for (int ul = 0; ul < 4; ++ul) {
                    const ulonglong2* wp =
                        (const ulonglong2*)(sm + OFF_W2 + (u0 + h * 4 + ul) * 16 + v0);
                    ulonglong2 wa = wp[0], wb = wp[1];
#pragma unroll
                    for (int i = 0; i < 5; ++i) {
                        u64 xs2 = dup2(xe[ul * 5 + i]);
                        A[i * 4 + 0] = ffma2(xs2, wa.x, A[i * 4 + 0]);
                        A[i * 4 + 1] = ffma2(xs2, wa.y, A[i * 4 + 1]);
                        A[i * 4 + 2] = ffma2(xs2, wb.x, A[i * 4 + 2]);
                        A[i * 4 + 3] = ffma2(xs2, wb.y, A[i * 4 + 3]);
                    }
                }
            }
        }
    }

    __syncthreads();   // all compute done before reusing x buffers as y storage

    // ---- two-pass u-half reduction into per-node y buffer (177 floats/node) ----
    float* yb = sm + node * 177;
    auto dump = [&](bool add) {
        if (type == 0) {
            const int v0 = vhalf * 24;
#pragma unroll
            for (int j = 0; j < 12; ++j) {
                float lo, hi; unpack2(A[j], lo, hi);
                if (add) { yb[v0 + 2*j] += lo; yb[v0 + 2*j + 1] += hi; }
                else     { yb[v0 + 2*j]  = lo; yb[v0 + 2*j + 1]  = hi; }
            }
        } else if (type == 1) {
            const int v0 = vhalf * 8;
#pragma unroll
            for (int i = 0; i < 3; ++i)
#pragma unroll
                for (int vp = 0; vp < 4; ++vp) {
                    float lo, hi; unpack2(A[i * 4 + vp], lo, hi);
                    int i0 = 48 + (v0 + 2*vp) * 3 + i;
                    int i1 = 48 + (v0 + 2*vp + 1) * 3 + i;
                    if (add) { yb[i0] += lo; yb[i1] += hi; }
                    else     { yb[i0]  = lo; yb[i1]  = hi; }
                }
        } else {
            const int v0 = vhalf * 8;
#pragma unroll
            for (int i = 0; i < 5; ++i)
#pragma unroll
                for (int vp = 0; vp < 4; ++vp) {
                    float lo, hi; unpack2(A[i * 4 + vp], lo, hi);
                    int i0 = 96 + (v0 + 2*vp) * 5 + i;
                    int i1 = 96 + (v0 + 2*vp + 1) * 5 + i;
                    if (add) { yb[i0] += lo; yb[i1] += hi; }
                    else     { yb[i0]  = lo; yb[i1]  = hi; }
                }
        }
    };
    if (uhalf == 0) dump(false);
    __syncthreads();
    if (uhalf == 1) dump(true);
    __syncthreads();

    // ---- epilogue: silu + second layer, 9 outputs per node ----
    if (tid < 9 * NODES) {
        const int nd = tid / 9, k = tid - nd * 9;
        const float* yn = sm + nd * 177;
        const float inv_in = 0.08838834764831845f;   // 1/sqrt(128)
        float o = 0.f;
        if (k == 0) {
#pragma unroll
            for (int h = 0; h < 16; ++h) {
                float v = yn[h] * inv_in;
                float s = v / (1.f + __expf(-v));
                o += s * sm[OFF_W2S + h];
            }
        } else if (k < 4) {
            const int i = k - 1;
#pragma unroll
            for (int v = 0; v < 16; ++v) {
                float gv = yn[16 + v] * inv_in;
                float g  = gv / (1.f + __expf(-gv));
                o += (yn[48 + v * 3 + i] * inv_in) * g * sm[OFF_W2S + 16 + v];
            }
        } else {
            const int i = k - 4;
#pragma unroll
            for (int v = 0; v < 16; ++v) {
                float gv = yn[32 + v] * inv_in;
                float g  = gv / (1.f + __expf(-gv));
                o += (yn[96 + v * 5 + i] * inv_in) * g * sm[OFF_W2S + 32 + v];
            }
        }
        const int gn = node0 + nd;
        if (gn < n) out[gn * 9 + k] = o * 0.25f;   // 1/sqrt(16)
    }
}

extern "C" void kernel_launch(void* const* d_in, const int* in_sizes, int n_in,
                              void* d_out, int out_size)
{
    const float* x    = (const float*)d_in[0];
    const float* w1_0 = (const float*)d_in[1];
    const float* w1_1 = (const float*)d_in[2];
    const float* w1_2 = (const float*)d_in[3];
    const float* w2_0 = (const float*)d_in[4];
    const float* w2_1 = (const float*)d_in[5];
    const float* w2_2 = (const float*)d_in[6];
    float* out = (float*)d_out;

    const int n = in_sizes[0] / 1152;
    const int smem = SM_FLOATS * (int)sizeof(float);   // 97984 B
    cudaFuncSetAttribute(readout_kernel, cudaFuncAttributeMaxDynamicSharedMemorySize, smem);
    const int blocks = (n + NODES - 1) / NODES;
    readout_kernel<<<blocks, TPB, smem>>>(x, w1_0, w1_1, w1_2, w2_0, w2_1, w2_2, out, n);
}

// round 7
// speedup vs baseline: 1.0106x; 1.0106x over previous
#include <cuda_runtime.h>

#define TPB     512
#define NODES   32
#define KU      16                  // u per chunk
#define NCHUNK  8
#define XS      148                 // floats per node per chunk: x0(16)+x1(48)+x2(80)+pad(4)
#define XBUF    (NODES * XS)        // 4736 floats per buffer
#define OFF_W0  (3 * XBUF)          // w1_0: 6144 floats
#define OFF_W1  (OFF_W0 + 6144)
#define OFF_W2  (OFF_W1 + 2048)
#define OFF_W2S (OFF_W2 + 2048)
#define SM_FLOATS (OFF_W2S + 48)    // 24496 floats = 97984 B -> 2 blocks/SM

typedef unsigned long long u64;

__device__ __forceinline__ u64 ffma2(u64 a, u64 b, u64 c) {
    u64 d;
    asm("fma.rn.f32x2 %0, %1, %2, %3;" : "=l"(d) : "l"(a), "l"(b), "l"(c));
    return d;
}
__device__ __forceinline__ u64 dup2(float v) {
    u64 d; unsigned u = __float_as_uint(v);
    asm("mov.b64 %0, {%1, %1};" : "=l"(d) : "r"(u));
    return d;
}
__device__ __forceinline__ void unpack2(u64 a, float& lo, float& hi) {
    lo = __uint_as_float((unsigned)a);
    hi = __uint_as_float((unsigned)(a >> 32));
}

__global__ void __launch_bounds__(TPB, 2)
readout_kernel(const float* __restrict__ x,
               const float* __restrict__ w1_0, const float* __restrict__ w1_1,
               const float* __restrict__ w1_2, const float* __restrict__ w2_0,
               const float* __restrict__ w2_1, const float* __restrict__ w2_2,
               float* __restrict__ out, int n)
{
    extern __shared__ float sm[];
    const int tid = threadIdx.x;
    const int node0 = blockIdx.x * NODES;
    const unsigned smbase = (unsigned)__cvta_generic_to_shared(sm);

    // ---- cp.async staging: 1152 x 16B per chunk over 512 threads ----
    // per node per chunk: 36 x 16B = x0(4) + x1(12) + x2(20)
    int gnd[3], sb[3], sc[3];
    unsigned sdst[3];
#pragma unroll
    for (int k = 0; k < 3; ++k) {
        int f = tid + k * TPB;
        if (f >= 36 * NODES) { gnd[k] = -1; sb[k] = 0; sc[k] = 0; sdst[k] = 0; continue; }
        int nd = f / 36, r = f - nd * 36;
        int dl;
        if (r < 4)       { sb[k] = 4 * r;               sc[k] = 16; dl = 4 * r; }
        else if (r < 16) { sb[k] = 128 + 4 * (r - 4);   sc[k] = 48; dl = 16 + 4 * (r - 4); }
        else             { sb[k] = 512 + 4 * (r - 16);  sc[k] = 80; dl = 64 + 4 * (r - 16); }
        int gn = node0 + nd;
        gnd[k] = (gn < n) ? gn : (n - 1);   // clamp (stores are guarded)
        sdst[k] = (unsigned)((nd * XS + dl) * 4);
    }
    auto stage = [&](int c, int buf) {
#pragma unroll
        for (int k = 0; k < 3; ++k) {
            if (gnd[k] < 0) break;
            const float* src = x + (size_t)gnd[k] * 1152 + sb[k] + sc[k] * c;
            unsigned dst = smbase + (unsigned)(buf * XBUF * 4) + sdst[k];
            asm volatile("cp.async.cg.shared.global [%0], [%1], 16;"
                         :: "r"(dst), "l"(src));
        }
    };

    stage(0, 0); asm volatile("cp.async.commit_group;" ::: "memory");
    stage(1, 1); asm volatile("cp.async.commit_group;" ::: "memory");

    for (int i = tid; i < 6144; i += TPB) sm[OFF_W0 + i] = w1_0[i];
    for (int i = tid; i < 2048; i += TPB) sm[OFF_W1 + i] = w1_1[i];
    for (int i = tid; i < 2048; i += TPB) sm[OFF_W2 + i] = w1_2[i];
    if (tid < 16) {
        sm[OFF_W2S + tid]      = w2_0[tid];
        sm[OFF_W2S + 16 + tid] = w2_1[tid];
        sm[OFF_W2S + 32 + tid] = w2_2[tid];
    }

    // warp roles: w0-3 y0 (12v), w4-7 y1 (4v), w8-15 y2 (2v)
    // SMSP gets {y0, y1, y2, y2} -> balanced 352 fma2/chunk/SMSP
    const int w    = tid >> 5;
    const int lane = tid & 31;
    const int node = lane;

    u64 A[6];
#pragma unroll
    for (int i = 0; i < 6; ++i) A[i] = 0ull;
    u64 B[4];
#pragma unroll
    for (int i = 0; i < 4; ++i) B[i] = 0ull;   // y2 uses A[5]=..A? use A[0..4]+B? see below

#pragma unroll 1
    for (int c = 0; c < NCHUNK; ++c) {
        if (c == NCHUNK - 1) asm volatile("cp.async.wait_group 0;" ::: "memory");
        else                 asm volatile("cp.async.wait_group 1;" ::: "memory");
        __syncthreads();
        if (c < NCHUNK - 2) {
            stage(c + 2, (c + 2) % 3);
            asm volatile("cp.async.commit_group;" ::: "memory");
        }
        const float* xr = sm + (c % 3) * XBUF + node * XS;
        const int u0 = KU * c;

        if (w < 4) {
            // y0: 12 outputs (w*12 .. +11) as 6 f32x2 pairs
            const int v0 = w * 12;
#pragma unroll
            for (int g = 0; g < 4; ++g) {
                float4 xv = *(const float4*)(xr + 4 * g);
                float xe[4] = { xv.x, xv.y, xv.z, xv.w };
#pragma unroll
                for (int du = 0; du < 4; ++du) {
                    u64 xs2 = dup2(xe[du]);
                    const ulonglong2* wp =
                        (const ulonglong2*)(sm + OFF_W0 + (u0 + 4 * g + du) * 48 + v0);
                    ulonglong2 p0 = wp[0], p1 = wp[1], p2 = wp[2];
                    A[0] = ffma2(xs2, p0.x, A[0]); A[1] = ffma2(xs2, p0.y, A[1]);
                    A[2] = ffma2(xs2, p1.x, A[2]); A[3] = ffma2(xs2, p1.y, A[3]);
                    A[4] = ffma2(xs2, p2.x, A[4]); A[5] = ffma2(xs2, p2.y, A[5]);
                }
            }
        } else if (w < 8) {
            // y1: 4 v ((w-4)*4..+3) x i=0..2 -> A[i*2+vp]
            const int v0 = (w - 4) * 4;
#pragma unroll
            for (int g = 0; g < 4; ++g) {
                const float4* xp = (const float4*)(xr + 16 + 12 * g);
                float4 q0 = xp[0], q1 = xp[1], q2 = xp[2];
                float xe[12] = { q0.x,q0.y,q0.z,q0.w, q1.x,q1.y,q1.z,q1.w,
                                 q2.x,q2.y,q2.z,q2.w };
#pragma unroll
                for (int du = 0; du < 4; ++du) {
                    ulonglong2 wv =
                        *(const ulonglong2*)(sm + OFF_W1 + (u0 + 4 * g + du) * 16 + v0);
#pragma unroll
                    for (int i = 0; i < 3; ++i) {
                        u64 xs2 = dup2(xe[du * 3 + i]);
                        A[i * 2 + 0] = ffma2(xs2, wv.x, A[i * 2 + 0]);
                        A[i * 2 + 1] = ffma2(xs2, wv.y, A[i * 2 + 1]);
                    }
                }
            }
        } else {
            // y2: 2 v ((w-8)*2, +1) x i=0..4 -> A[0..4] (i<5? use A[0..4] and B unused pad)
            const int v0 = (w - 8) * 2;
#pragma unroll
            for (int g = 0; g < 4; ++g) {
                const float4* xp = (const float4*)(xr + 64 + 20 * g);
                float4 q0 = xp[0], q1 = xp[1], q2 = xp[2], q3 = xp[3], q4 = xp[4];
                float xe[20] = { q0.x,q0.y,q0.z,q0.w, q1.x,q1.y,q1.z,q1.w,
                                 q2.x,q2.y,q2.z,q2.w, q3.x,q3.y,q3.z,q3.w,
                                 q4.x,q4.y,q4.z,q4.w };
#pragma unroll
                for (int du = 0; du < 4; ++du) {
                    u64 wv = *(const u64*)(sm + OFF_W2 + (u0 + 4 * g + du) * 16 + v0);
#pragma unroll
                    for (int i = 0; i < 5; ++i) {
                        u64 xs2 = dup2(xe[du * 5 + i]);
                        if (i < 4) B[i] = ffma2(xs2, wv, B[i]);
                        else       A[0] = ffma2(xs2, wv, A[0]);
                    }
                }
            }
        }
    }

    __syncthreads();   // all compute done before reusing x buffers as y storage

    // ---- dump accumulators into per-node y buffer (177 floats/node) ----
    {
        float* yb = sm + node * 177;
        if (w < 4) {
            const int v0 = w * 12;
#pragma unroll
            for (int j = 0; j < 6; ++j) {
                float lo, hi; unpack2(A[j], lo, hi);
                yb[v0 + 2 * j] = lo; yb[v0 + 2 * j + 1] = hi;
            }
        } else if (w < 8) {
            const int v0 = (w - 4) * 4;
#pragma unroll
            for (int i = 0; i < 3; ++i)
#pragma unroll
                for (int vp = 0; vp < 2; ++vp) {
                    float lo, hi; unpack2(A[i * 2 + vp], lo, hi);
                    yb[48 + (v0 + 2 * vp) * 3 + i]     = lo;
                    yb[48 + (v0 + 2 * vp + 1) * 3 + i] = hi;
                }
        } else {
            const int v0 = (w - 8) * 2;
#pragma unroll
            for (int i = 0; i < 5; ++i) {
                float lo, hi;
                if (i < 4) unpack2(B[i], lo, hi);
                else       unpack2(A[0], lo, hi);
                yb[96 + v0 * 5 + i]       = lo;
                yb[96 + (v0 + 1) * 5 + i] = hi;
            }
        }
    }
    __syncthreads();

    // ---- epilogue: silu + second layer, 9 outputs per node ----
    if (tid < 9 * NODES) {
        const int nd = tid / 9, k = tid - nd * 9;
        const float* yn = sm + nd * 177;
        const float inv_in = 0.08838834764831845f;   // 1/sqrt(128)
        float o = 0.f;
        if (k == 0) {
#pragma unroll
            for (int h = 0; h < 16; ++h) {
                float v = yn[h] * inv_in;
                float s = v / (1.f + __expf(-v));
                o += s * sm[OFF_W2S + h];
            }
        } else if (k < 4) {
            const int i = k - 1;
#pragma unroll
            for (int v = 0; v < 16; ++v) {
                float gv = yn[16 + v] * inv_in;
                float g  = gv / (1.f + __expf(-gv));
                o += (yn[48 + v * 3 + i] * inv_in) * g * sm[OFF_W2S + 16 + v];
            }
        } else {
            const int i = k - 4;
#pragma unroll
            for (int v = 0; v < 16; ++v) {
                float gv = yn[32 + v] * inv_in;
                float g  = gv / (1.f + __expf(-gv));
                o += (yn[96 + v * 5 + i] * inv_in) * g * sm[OFF_W2S + 32 + v];
            }
        }
        const int gn = node0 + nd;
        if (gn < n) out[gn * 9 + k] = o * 0.25f;   // 1/sqrt(16)
    }
}

extern "C" void kernel_launch(void* const* d_in, const int* in_sizes, int n_in,
                              void* d_out, int out_size)
{
    const float* x    = (const float*)d_in[0];
    const float* w1_0 = (const float*)d_in[1];
    const float* w1_1 = (const float*)d_in[2];
    const float* w1_2 = (const float*)d_in[3];
    const float* w2_0 = (const float*)d_in[4];
    const float* w2_1 = (const float*)d_in[5];
    const float* w2_2 = (const float*)d_in[6];
    float* out = (float*)d_out;

    const int n = in_sizes[0] / 1152;
    const int smem = SM_FLOATS * (int)sizeof(float);   // 97984 B
    cudaFuncSetAttribute(readout_kernel, cudaFuncAttributeMaxDynamicSharedMemorySize, smem);
    const int blocks = (n + NODES - 1) / NODES;
    readout_kernel<<<blocks, TPB, smem>>>(x, w1_0, w1_1, w1_2, w2_0, w2_1, w2_2, out, n);
}